// round 3
// baseline (speedup 1.0000x reference)
#include <cuda_runtime.h>

#define NN 50000
#define NM 4
#define DD 128
#define NE 800000
#define ALPHA 0.05f
#define EPS 1e-5f

// f32x2 packed FMA (Blackwell): lanewise fp32 on 64-bit register pairs.
#define FMA_F32X2(out, a, b, c) \
    asm("fma.rn.f32x2 %0, %1, %2, %3;" : "=l"(out) : "l"(a), "l"(b), "l"(c))
#define PACK_F32X2(out, lo, hi) \
    asm("mov.b64 %0, {%1, %2};" : "=l"(out) : "f"(lo), "f"(hi))
#define UNPACK_F32X2(lo, hi, in) \
    asm("mov.b64 {%0, %1}, %2;" : "=f"(lo), "=f"(hi) : "l"(in))

// ---------------------------------------------------------------------------
// Scratch (device globals; no runtime allocation)
// ---------------------------------------------------------------------------
__device__ int   g_count[NN];
__device__ int   g_off[NN + 1];
__device__ int   g_cursor[NN];
__device__ int   g_src_s[NE];                 // src ids sorted by dst
__device__ float g_w_s[NE];                   // weights sorted by dst
__device__ int   g_bsum[64];                  // per-block scan sums
__device__ int   g_bbase[64];                 // exclusive-scanned block bases
__device__ unsigned long long g_Wp[64 * 32 * 4];  // k-pair-packed W, 64 KB

// ---------------------------------------------------------------------------
// CSR build
// ---------------------------------------------------------------------------
__global__ void zero_counts_kernel() {
    int i = blockIdx.x * blockDim.x + threadIdx.x;
    if (i < NN) g_count[i] = 0;
}

__global__ void hist_kernel(const int* __restrict__ dst) {
    int e = blockIdx.x * blockDim.x + threadIdx.x;
    if (e < NE) atomicAdd(&g_count[dst[e]], 1);
}

// scan1: per-block (1024) exclusive scan of counts; block totals to g_bsum.
__global__ void __launch_bounds__(1024) scan1_kernel() {
    __shared__ int s[1024];
    int i = blockIdx.x * 1024 + threadIdx.x;
    int v = (i < NN) ? g_count[i] : 0;
    s[threadIdx.x] = v;
    __syncthreads();
#pragma unroll
    for (int o = 1; o < 1024; o <<= 1) {
        int t = (threadIdx.x >= o) ? s[threadIdx.x - o] : 0;
        __syncthreads();
        s[threadIdx.x] += t;
        __syncthreads();
    }
    if (i < NN) g_off[i] = s[threadIdx.x] - v;   // block-local exclusive
    if (threadIdx.x == 1023) g_bsum[blockIdx.x] = s[1023];
}

// scan2: single block scans the 49 block sums.
__global__ void scan2_kernel(int nblocks) {
    __shared__ int s[64];
    int v = (threadIdx.x < nblocks) ? g_bsum[threadIdx.x] : 0;
    s[threadIdx.x] = v;
    __syncthreads();
#pragma unroll
    for (int o = 1; o < 64; o <<= 1) {
        int t = (threadIdx.x >= o) ? s[threadIdx.x - o] : 0;
        __syncthreads();
        s[threadIdx.x] += t;
        __syncthreads();
    }
    g_bbase[threadIdx.x] = s[threadIdx.x] - v;   // exclusive base
    if (threadIdx.x == 0) g_off[NN] = s[63];     // grand total
}

// scan3: add block bases; init cursors.
__global__ void __launch_bounds__(1024) scan3_kernel() {
    int i = blockIdx.x * 1024 + threadIdx.x;
    if (i < NN) {
        int o = g_off[i] + g_bbase[blockIdx.x];
        g_off[i] = o;
        g_cursor[i] = o;
    }
}

__global__ void fill_csr_kernel(const int* __restrict__ src,
                                const int* __restrict__ dst,
                                const float* __restrict__ w) {
    int e = blockIdx.x * blockDim.x + threadIdx.x;
    if (e < NE) {
        int t = dst[e];
        int pos = atomicAdd(&g_cursor[t], 1);
        g_src_s[pos] = src[e];
        g_w_s[pos]  = w[e];
    }
}

// ---------------------------------------------------------------------------
// Pack W into k-pair-interleaved u64 layout:
//   g_Wp[(p*32 + j)*4 + c] = pack( W[2p][4j+c], W[2p+1][4j+c] )
// so ld.shared.b64 of (agg[2p], agg[2p+1]) multiplies it directly via f32x2.
// ---------------------------------------------------------------------------
__global__ void pack_W_kernel(const float* __restrict__ W) {
    int idx = blockIdx.x * blockDim.x + threadIdx.x;   // 0 .. 8191
    if (idx < 64 * 32 * 4) {
        int c = idx & 3;
        int j = (idx >> 2) & 31;
        int p = idx >> 7;
        int col = j * 4 + c;
        unsigned int lo = __float_as_uint(W[(2 * p) * DD + col]);
        unsigned int hi = __float_as_uint(W[(2 * p + 1) * DD + col]);
        g_Wp[idx] = ((unsigned long long)hi << 32) | lo;
    }
}

// ---------------------------------------------------------------------------
// Fused gather + GEMM + residual + LayerNorm. One CTA (128 thr) per node.
// ---------------------------------------------------------------------------
__global__ void __launch_bounds__(128) fused_kernel(
    const ulonglong2* __restrict__ x2,   // multimodal rows as 128×16B chunks
    const float*  __restrict__ xf,       // multimodal flat
    const float4* __restrict__ gamma4,   // 32 f4
    const float4* __restrict__ beta4,    // 32 f4
    float4* __restrict__ out4)           // [N*M, 32] f4
{
    const int node = blockIdx.x;
    const int tid  = threadIdx.x;

    const int begin = g_off[node];
    const int end   = g_off[node + 1];

    // Phase 1: gather-accumulate this thread's 16B slice of the agg row.
    unsigned long long accA = 0ull, accB = 0ull;
#pragma unroll 4
    for (int e = begin; e < end; e++) {
        int   s  = __ldg(&g_src_s[e]);
        float we = __ldg(&g_w_s[e]);
        unsigned long long wwe;
        PACK_F32X2(wwe, we, we);
        ulonglong2 v = __ldg(&x2[(size_t)s * 128 + tid]);
        FMA_F32X2(accA, v.x, wwe, accA);
        FMA_F32X2(accB, v.y, wwe, accB);
    }

    __shared__ float s_agg[NM][DD];
    {
        unsigned long long* s64 = reinterpret_cast<unsigned long long*>(&s_agg[0][0]);
        s64[tid * 2 + 0] = accA;
        s64[tid * 2 + 1] = accB;
    }
    __syncthreads();

    // Phase 2: warp m projects modality-row m by W (f32x2, k-pairs).
    const int warp = tid >> 5;   // modality 0..3
    const int lane = tid & 31;   // cols 4*lane .. 4*lane+3

    const unsigned long long* s_row64 =
        reinterpret_cast<const unsigned long long*>(&s_agg[warp][0]);
    const ulonglong2* Wp2 = reinterpret_cast<const ulonglong2*>(g_Wp);

    unsigned long long acc0 = 0ull, acc1 = 0ull, acc2 = 0ull, acc3 = 0ull;
#pragma unroll 8
    for (int p = 0; p < 64; p++) {
        unsigned long long apair = s_row64[p];            // (a[2p], a[2p+1])
        ulonglong2 w01 = __ldg(&Wp2[(p * 32 + lane) * 2 + 0]);
        ulonglong2 w23 = __ldg(&Wp2[(p * 32 + lane) * 2 + 1]);
        FMA_F32X2(acc0, w01.x, apair, acc0);
        FMA_F32X2(acc1, w01.y, apair, acc1);
        FMA_F32X2(acc2, w23.x, apair, acc2);
        FMA_F32X2(acc3, w23.y, apair, acc3);
    }

    float l0, h0, l1, h1, l2, h2, l3, h3;
    UNPACK_F32X2(l0, h0, acc0);
    UNPACK_F32X2(l1, h1, acc1);
    UNPACK_F32X2(l2, h2, acc2);
    UNPACK_F32X2(l3, h3, acc3);
    float a0 = l0 + h0, a1 = l1 + h1, a2 = l2 + h2, a3 = l3 + h3;

    const size_t rowg = (size_t)node * NM + warp;
    float4 xv = __ldg(reinterpret_cast<const float4*>(xf) + rowg * 32 + lane);

    float y0 = fmaf(ALPHA, a0, xv.x);
    float y1 = fmaf(ALPHA, a1, xv.y);
    float y2 = fmaf(ALPHA, a2, xv.z);
    float y3 = fmaf(ALPHA, a3, xv.w);

    // Warp-level LayerNorm over 128 columns (4 per lane)
    float s  = y0 + y1 + y2 + y3;
    float ss = y0 * y0 + y1 * y1 + y2 * y2 + y3 * y3;
#pragma unroll
    for (int o = 16; o > 0; o >>= 1) {
        s  += __shfl_xor_sync(0xFFFFFFFFu, s, o);
        ss += __shfl_xor_sync(0xFFFFFFFFu, ss, o);
    }
    const float inv_d = 1.f / (float)DD;
    float mu  = s * inv_d;
    float var = ss * inv_d - mu * mu;
    float inv = rsqrtf(var + EPS);

    float4 g = __ldg(&gamma4[lane]);
    float4 b = __ldg(&beta4[lane]);
    float4 o4;
    o4.x = fmaf((y0 - mu) * inv, g.x, b.x);
    o4.y = fmaf((y1 - mu) * inv, g.y, b.y);
    o4.z = fmaf((y2 - mu) * inv, g.z, b.z);
    o4.w = fmaf((y3 - mu) * inv, g.w, b.w);
    out4[rowg * 32 + lane] = o4;
}

// ---------------------------------------------------------------------------
extern "C" void kernel_launch(void* const* d_in, const int* in_sizes, int n_in,
                              void* d_out, int out_size) {
    const float* multimodal = (const float*)d_in[0];  // [N, M, D] fp32
    const int*   edge_src   = (const int*)d_in[1];    // [E]
    const int*   edge_dst   = (const int*)d_in[2];    // [E]
    const float* edge_w     = (const float*)d_in[3];  // [E]
    const float* W          = (const float*)d_in[4];  // [D, D]
    const float* gamma      = (const float*)d_in[5];  // [D]
    const float* beta       = (const float*)d_in[6];  // [D]
    float* out = (float*)d_out;

    const int SCAN_BLOCKS = (NN + 1023) / 1024;  // 49

    zero_counts_kernel<<<(NN + 255) / 256, 256>>>();
    pack_W_kernel<<<(64 * 32 * 4 + 255) / 256, 256>>>(W);
    hist_kernel<<<(NE + 255) / 256, 256>>>(edge_dst);
    scan1_kernel<<<SCAN_BLOCKS, 1024>>>();
    scan2_kernel<<<1, 64>>>(SCAN_BLOCKS);
    scan3_kernel<<<SCAN_BLOCKS, 1024>>>();
    fill_csr_kernel<<<(NE + 255) / 256, 256>>>(edge_src, edge_dst, edge_w);

    fused_kernel<<<NN, 128>>>(
        (const ulonglong2*)multimodal, multimodal,
        (const float4*)gamma, (const float4*)beta,
        (float4*)out);
}

// round 4
// speedup vs baseline: 2.5272x; 2.5272x over previous
#include <cuda_runtime.h>

#define NN 50000
#define NM 4
#define DD 128
#define NE 800000
#define ALPHA 0.05f
#define EPS 1e-5f

// ---------------------------------------------------------------------------
// Scratch (device globals; no runtime allocation)
// ---------------------------------------------------------------------------
__device__ int   g_count[NN];
__device__ int   g_off[NN + 1];
__device__ int   g_cursor[NN];
__device__ int   g_src_s[NE];   // src ids sorted by dst
__device__ float g_w_s[NE];     // weights sorted by dst
__device__ int   g_bsum[64];
__device__ int   g_bbase[64];

// ---------------------------------------------------------------------------
// CSR build
// ---------------------------------------------------------------------------
__global__ void zero_counts_kernel() {
    int i = blockIdx.x * blockDim.x + threadIdx.x;
    if (i < NN) g_count[i] = 0;
}

__global__ void hist_kernel(const int* __restrict__ dst) {
    int e = blockIdx.x * blockDim.x + threadIdx.x;
    if (e < NE) atomicAdd(&g_count[dst[e]], 1);
}

// scan1: per-block (1024) exclusive scan of counts; block totals to g_bsum.
__global__ void __launch_bounds__(1024) scan1_kernel() {
    __shared__ int s[1024];
    int i = blockIdx.x * 1024 + threadIdx.x;
    int v = (i < NN) ? g_count[i] : 0;
    s[threadIdx.x] = v;
    __syncthreads();
#pragma unroll
    for (int o = 1; o < 1024; o <<= 1) {
        int t = (threadIdx.x >= o) ? s[threadIdx.x - o] : 0;
        __syncthreads();
        s[threadIdx.x] += t;
        __syncthreads();
    }
    if (i < NN) g_off[i] = s[threadIdx.x] - v;   // block-local exclusive
    if (threadIdx.x == 1023) g_bsum[blockIdx.x] = s[1023];
}

// scan2: single block scans the block sums.
__global__ void scan2_kernel(int nblocks) {
    __shared__ int s[64];
    int v = (threadIdx.x < nblocks) ? g_bsum[threadIdx.x] : 0;
    s[threadIdx.x] = v;
    __syncthreads();
#pragma unroll
    for (int o = 1; o < 64; o <<= 1) {
        int t = (threadIdx.x >= o) ? s[threadIdx.x - o] : 0;
        __syncthreads();
        s[threadIdx.x] += t;
        __syncthreads();
    }
    g_bbase[threadIdx.x] = s[threadIdx.x] - v;
    if (threadIdx.x == 0) g_off[NN] = s[63];
}

// scan3: add block bases; init cursors.
__global__ void __launch_bounds__(1024) scan3_kernel() {
    int i = blockIdx.x * 1024 + threadIdx.x;
    if (i < NN) {
        int o = g_off[i] + g_bbase[blockIdx.x];
        g_off[i] = o;
        g_cursor[i] = o;
    }
}

__global__ void fill_csr_kernel(const int* __restrict__ src,
                                const int* __restrict__ dst,
                                const float* __restrict__ w) {
    int e = blockIdx.x * blockDim.x + threadIdx.x;
    if (e < NE) {
        int t = dst[e];
        int pos = atomicAdd(&g_cursor[t], 1);
        g_src_s[pos] = src[e];
        g_w_s[pos]  = w[e];
    }
}

// ---------------------------------------------------------------------------
// Fused gather + GEMM + residual + LayerNorm. One CTA (128 thr) per node.
//   Phase 1: each thread accumulates one float4 slice of the 512-float agg
//            row over the node's incoming edges (coalesced row reads).
//   Phase 2: k-split GEMM — warp w covers k in [32w, 32w+32) for ALL 4
//            modality rows (16 FMAs per W float4 load), partials to smem.
//   Phase 3: cross-warp reduce; warp m finishes modality m: residual + LN.
// ---------------------------------------------------------------------------
__global__ void __launch_bounds__(128) fused_kernel(
    const float4* __restrict__ x4,     // multimodal rows = 128 f4
    const float*  __restrict__ xf,     // multimodal flat
    const float4* __restrict__ W4,     // W rows = 32 f4
    const float4* __restrict__ gamma4,
    const float4* __restrict__ beta4,
    float4* __restrict__ out4)         // [N*M, 32] f4
{
    const int node = blockIdx.x;
    const int tid  = threadIdx.x;
    const int warp = tid >> 5;
    const int lane = tid & 31;

    const int begin = g_off[node];
    const int end   = g_off[node + 1];

    // ---- Phase 1: gather-accumulate ----
    float4 acc = make_float4(0.f, 0.f, 0.f, 0.f);
#pragma unroll 4
    for (int e = begin; e < end; e++) {
        int   s  = g_src_s[e];
        float we = g_w_s[e];
        float4 v = x4[(size_t)s * (NM * DD / 4) + tid];
        acc.x = fmaf(we, v.x, acc.x);
        acc.y = fmaf(we, v.y, acc.y);
        acc.z = fmaf(we, v.z, acc.z);
        acc.w = fmaf(we, v.w, acc.w);
    }

    __shared__ float  s_agg[NM][DD];
    __shared__ float4 s_part[4][NM][32];   // [warp][modality][col/4] — 8 KB

    reinterpret_cast<float4*>(&s_agg[0][0])[tid] = acc;
    __syncthreads();

    // ---- Phase 2: k-split GEMM ----
    float4 p0 = make_float4(0.f, 0.f, 0.f, 0.f);
    float4 p1 = make_float4(0.f, 0.f, 0.f, 0.f);
    float4 p2 = make_float4(0.f, 0.f, 0.f, 0.f);
    float4 p3 = make_float4(0.f, 0.f, 0.f, 0.f);

    const int kbase = warp * 32;
#pragma unroll 8
    for (int kk = 0; kk < 32; kk++) {
        const int k = kbase + kk;
        float4 wv = __ldg(&W4[k * 32 + lane]);
        float a0 = s_agg[0][k];
        float a1 = s_agg[1][k];
        float a2 = s_agg[2][k];
        float a3 = s_agg[3][k];
        p0.x = fmaf(a0, wv.x, p0.x); p0.y = fmaf(a0, wv.y, p0.y);
        p0.z = fmaf(a0, wv.z, p0.z); p0.w = fmaf(a0, wv.w, p0.w);
        p1.x = fmaf(a1, wv.x, p1.x); p1.y = fmaf(a1, wv.y, p1.y);
        p1.z = fmaf(a1, wv.z, p1.z); p1.w = fmaf(a1, wv.w, p1.w);
        p2.x = fmaf(a2, wv.x, p2.x); p2.y = fmaf(a2, wv.y, p2.y);
        p2.z = fmaf(a2, wv.z, p2.z); p2.w = fmaf(a2, wv.w, p2.w);
        p3.x = fmaf(a3, wv.x, p3.x); p3.y = fmaf(a3, wv.y, p3.y);
        p3.z = fmaf(a3, wv.z, p3.z); p3.w = fmaf(a3, wv.w, p3.w);
    }
    s_part[warp][0][lane] = p0;
    s_part[warp][1][lane] = p1;
    s_part[warp][2][lane] = p2;
    s_part[warp][3][lane] = p3;
    __syncthreads();

    // ---- Phase 3: reduce partials; warp m finishes modality m ----
    float4 q0 = s_part[0][warp][lane];
    float4 q1 = s_part[1][warp][lane];
    float4 q2 = s_part[2][warp][lane];
    float4 q3 = s_part[3][warp][lane];
    float a0 = (q0.x + q1.x) + (q2.x + q3.x);
    float a1 = (q0.y + q1.y) + (q2.y + q3.y);
    float a2 = (q0.z + q1.z) + (q2.z + q3.z);
    float a3 = (q0.w + q1.w) + (q2.w + q3.w);

    const size_t rowg = (size_t)node * NM + warp;
    float4 xv = __ldg(reinterpret_cast<const float4*>(xf) + rowg * 32 + lane);

    float y0 = fmaf(ALPHA, a0, xv.x);
    float y1 = fmaf(ALPHA, a1, xv.y);
    float y2 = fmaf(ALPHA, a2, xv.z);
    float y3 = fmaf(ALPHA, a3, xv.w);

    // Warp-level LayerNorm over 128 columns (4 per lane)
    float s  = y0 + y1 + y2 + y3;
    float ss = y0 * y0 + y1 * y1 + y2 * y2 + y3 * y3;
#pragma unroll
    for (int o = 16; o > 0; o >>= 1) {
        s  += __shfl_xor_sync(0xFFFFFFFFu, s, o);
        ss += __shfl_xor_sync(0xFFFFFFFFu, ss, o);
    }
    const float inv_d = 1.f / (float)DD;
    float mu  = s * inv_d;
    float var = ss * inv_d - mu * mu;
    float inv = rsqrtf(var + EPS);

    float4 g = __ldg(&gamma4[lane]);
    float4 b = __ldg(&beta4[lane]);
    float4 o4;
    o4.x = fmaf((y0 - mu) * inv, g.x, b.x);
    o4.y = fmaf((y1 - mu) * inv, g.y, b.y);
    o4.z = fmaf((y2 - mu) * inv, g.z, b.z);
    o4.w = fmaf((y3 - mu) * inv, g.w, b.w);
    out4[rowg * 32 + lane] = o4;
}

// ---------------------------------------------------------------------------
extern "C" void kernel_launch(void* const* d_in, const int* in_sizes, int n_in,
                              void* d_out, int out_size) {
    const float* multimodal = (const float*)d_in[0];  // [N, M, D] fp32
    const int*   edge_src   = (const int*)d_in[1];    // [E]
    const int*   edge_dst   = (const int*)d_in[2];    // [E]
    const float* edge_w     = (const float*)d_in[3];  // [E]
    const float* W          = (const float*)d_in[4];  // [D, D]
    const float* gamma      = (const float*)d_in[5];  // [D]
    const float* beta       = (const float*)d_in[6];  // [D]
    float* out = (float*)d_out;

    const int SCAN_BLOCKS = (NN + 1023) / 1024;  // 49

    zero_counts_kernel<<<(NN + 255) / 256, 256>>>();
    hist_kernel<<<(NE + 255) / 256, 256>>>(edge_dst);
    scan1_kernel<<<SCAN_BLOCKS, 1024>>>();
    scan2_kernel<<<1, 64>>>(SCAN_BLOCKS);
    scan3_kernel<<<SCAN_BLOCKS, 1024>>>();
    fill_csr_kernel<<<(NE + 255) / 256, 256>>>(edge_src, edge_dst, edge_w);

    fused_kernel<<<NN, 128>>>(
        (const float4*)multimodal, multimodal,
        (const float4*)W, (const float4*)gamma, (const float4*)beta,
        (float4*)out);
}